// round 16
// baseline (speedup 1.0000x reference)
#include <cuda_runtime.h>
#include <cuda_fp16.h>
#include <cstdint>

#define H 1024
#define W 1024
#define TS 104          // square output tile (pixels)
#define G  10           // 10*104 = 1040 >= 1024 (both dims)
#define NB 16           // 8 pred + 8 target
#define NBLOCKS (G * G * NB)

typedef unsigned int u32;

__device__ float g_sums[4];
__device__ u32   g_done = 0;

__device__ __forceinline__ float sig_(float x) { return 1.0f / (1.0f + __expf(-x)); }

__device__ __forceinline__ u32 h2u(__half2 h) { return *reinterpret_cast<u32*>(&h); }
__device__ __forceinline__ __half2 u2h(u32 u) { return *reinterpret_cast<__half2*>(&u); }

// load 4 fp32 px, pad image-OOB with +1.0 (acts as +inf for erode; data in (0,1))
__device__ __forceinline__ float4 load_row(const float* __restrict__ img, int gy, int gx0, bool doSig)
{
    float4 v;
    if ((unsigned)gy < H) {
        const float* row = img + (size_t)gy * W;
        if (gx0 >= 0 && gx0 + 3 < W) {
            v = *reinterpret_cast<const float4*>(row + gx0);
            if (doSig) { v.x = sig_(v.x); v.y = sig_(v.y); v.z = sig_(v.z); v.w = sig_(v.w); }
        } else {
            v.x = ((unsigned)(gx0+0) < W) ? (doSig ? sig_(row[gx0+0]) : row[gx0+0]) : 1.0f;
            v.y = ((unsigned)(gx0+1) < W) ? (doSig ? sig_(row[gx0+1]) : row[gx0+1]) : 1.0f;
            v.z = ((unsigned)(gx0+2) < W) ? (doSig ? sig_(row[gx0+2]) : row[gx0+2]) : 1.0f;
            v.w = ((unsigned)(gx0+3) < W) ? (doSig ? sig_(row[gx0+3]) : row[gx0+3]) : 1.0f;
        }
    } else {
        v = make_float4(1.f, 1.f, 1.f, 1.f);
    }
    return v;
}

// buffer: 128 rows x 128 cols (fp16); warp w owns rows 4w..4w+3; lane = 4-px group.
__global__ __launch_bounds__(1024, 1)
void cl_main(const float* __restrict__ pred, const float* __restrict__ tgt,
             float* __restrict__ out)
{
    extern __shared__ uint2 smem_[];
    uint2* exA = smem_;           // [64][32] erode rowmin boundary rows
    uint2* exB = smem_ + 2048;    // [64][32] dilate rowmax boundary rows

    const int tid  = threadIdx.x;
    const int lane = tid & 31;
    const int wid  = tid >> 5;
    const int bx = blockIdx.x, by = blockIdx.y, b = blockIdx.z;
    const bool isPred = (b < 8);
    const float* img = isPred ? pred + (size_t)b * H * W
                              : tgt  + (size_t)(b - 8) * H * W;

    const int gx0 = bx * TS - 12 + 4 * lane;
    const int gy0 = by * TS - 12 + 4 * wid;
    const bool thrOOB = ((unsigned)gy0 > (unsigned)(H - 4)) ||
                        ((unsigned)gx0 > (unsigned)(W - 4));

    // keep-masks per half2 (0xFFFF per in-image px)
    u32 kma[4], kmb[4];
    {
        const u32 ca = (((unsigned)(gx0+0) < W) ? 0x0000FFFFu : 0u)
                     | (((unsigned)(gx0+1) < W) ? 0xFFFF0000u : 0u);
        const u32 cb = (((unsigned)(gx0+2) < W) ? 0x0000FFFFu : 0u)
                     | (((unsigned)(gx0+3) < W) ? 0xFFFF0000u : 0u);
        #pragma unroll
        for (int i = 0; i < 4; i++) {
            const bool rv = (unsigned)(gy0 + i) < H;
            kma[i] = rv ? ca : 0u;
            kmb[i] = rv ? cb : 0u;
        }
    }
    const u32 PADHI = 0x3C003C00u;  // (+1,+1) fp16 (erode pad)
    const u32 PADLO = 0xBC00BC00u;  // (-1,-1) fp16 (dilate pad)

    // ---- load e_0 ----
    __half2 ea[4], eb[4];
    #pragma unroll
    for (int i = 0; i < 4; i++) {
        float4 v = load_row(img, gy0 + i, gx0, isPred);
        ea[i] = __floats2half2_rn(v.x, v.y);
        eb[i] = __floats2half2_rn(v.z, v.w);
    }

    __half2 ska[4], skb[4];
    const __half2 h2z = __float2half2_rn(0.f);
    #pragma unroll
    for (int i = 0; i < 4; i++) { ska[i] = h2z; skb[i] = h2z; }

    const int upIdx = ((wid == 0)  ? 1       : (wid - 1) * 2 + 1) * 32 + lane;
    const int dnIdx = ((wid == 31) ? wid * 2 : (wid + 1) * 2) * 32 + lane;
    const int sl0 = (wid * 2 + 0) * 32 + lane;
    const int sl1 = (wid * 2 + 1) * 32 + lane;
    const bool dilateW = (wid >= 2) && (wid <= 29);
    const bool centerW = (wid >= 3) && (wid <= 28) && (lane >= 3) && (lane <= 28);

    #pragma unroll
    for (int k = 0; k < 11; k++) {
        // ---- erode horizontal: shuffles + PRMT shifts + HMNMX2 ----
        __half2 rma[4], rmb[4];
        #pragma unroll
        for (int i = 0; i < 4; i++) {
            u32 ua = h2u(ea[i]), ub = h2u(eb[i]);
            u32 lw = __shfl_up_sync(0xffffffffu, ub, 1);
            u32 rx = __shfl_down_sync(0xffffffffu, ua, 1);
            u32 la = __byte_perm(lw, ua, 0x5432);   // (p-1,p0)
            u32 mi = __byte_perm(ua, ub, 0x5432);   // (p1,p2)
            u32 rb = __byte_perm(ub, rx, 0x5432);   // (p3,p4)
            rma[i] = __hmin2(__hmin2(u2h(la), ea[i]), u2h(mi));
            rmb[i] = __hmin2(__hmin2(u2h(mi), eb[i]), u2h(rb));
        }
        exA[sl0] = make_uint2(h2u(rma[0]), h2u(rmb[0]));
        exA[sl1] = make_uint2(h2u(rma[3]), h2u(rmb[3]));
        __syncthreads();
        const uint2 upu = exA[upIdx];
        const uint2 dnu = exA[dnIdx];

        // ---- erode vertical (registers, CSE) ----
        __half2 m01a = __hmin2(rma[0], rma[1]), m23a = __hmin2(rma[2], rma[3]);
        __half2 m01b = __hmin2(rmb[0], rmb[1]), m23b = __hmin2(rmb[2], rmb[3]);
        __half2 ena[4], enb[4];
        ena[0] = __hmin2(u2h(upu.x), m01a);
        ena[1] = __hmin2(m01a, rma[2]);
        ena[2] = __hmin2(rma[1], m23a);
        ena[3] = __hmin2(m23a, u2h(dnu.x));
        enb[0] = __hmin2(u2h(upu.y), m01b);
        enb[1] = __hmin2(m01b, rmb[2]);
        enb[2] = __hmin2(rmb[1], m23b);
        enb[3] = __hmin2(m23b, u2h(dnu.y));

        // ---- forcing (border threads): dilate view pad=-1, erode view pad=+1 ----
        __half2 eda[4], edb[4];
        if (thrOOB) {
            #pragma unroll
            for (int i = 0; i < 4; i++) {
                u32 xa = h2u(ena[i]), xb = h2u(enb[i]);
                eda[i] = u2h((xa & kma[i]) | (PADLO & ~kma[i]));
                edb[i] = u2h((xb & kmb[i]) | (PADLO & ~kmb[i]));
                ena[i] = u2h((xa & kma[i]) | (PADHI & ~kma[i]));
                enb[i] = u2h((xb & kmb[i]) | (PADHI & ~kmb[i]));
            }
        } else {
            #pragma unroll
            for (int i = 0; i < 4; i++) { eda[i] = ena[i]; edb[i] = enb[i]; }
        }

        // ---- dilate horizontal + exchange (warps near center) ----
        __half2 xma[4], xmb[4];
        if (dilateW) {
            #pragma unroll
            for (int i = 0; i < 4; i++) {
                u32 ua = h2u(eda[i]), ub = h2u(edb[i]);
                u32 lw = __shfl_up_sync(0xffffffffu, ub, 1);
                u32 rx = __shfl_down_sync(0xffffffffu, ua, 1);
                u32 la = __byte_perm(lw, ua, 0x5432);
                u32 mi = __byte_perm(ua, ub, 0x5432);
                u32 rb = __byte_perm(ub, rx, 0x5432);
                xma[i] = __hmax2(__hmax2(u2h(la), eda[i]), u2h(mi));
                xmb[i] = __hmax2(__hmax2(u2h(mi), edb[i]), u2h(rb));
            }
            exB[sl0] = make_uint2(h2u(xma[0]), h2u(xmb[0]));
            exB[sl1] = make_uint2(h2u(xma[3]), h2u(xmb[3]));
        }
        __syncthreads();

        // ---- dilate vertical -> open; delta; skel update (relu dropped: exact) ----
        if (centerW) {
            const uint2 uu = exB[upIdx];
            const uint2 dd = exB[dnIdx];
            __half2 x01a = __hmax2(xma[0], xma[1]), x23a = __hmax2(xma[2], xma[3]);
            __half2 x01b = __hmax2(xmb[0], xmb[1]), x23b = __hmax2(xmb[2], xmb[3]);
            __half2 opa[4], opb[4];
            opa[0] = __hmax2(u2h(uu.x), x01a);
            opa[1] = __hmax2(x01a, xma[2]);
            opa[2] = __hmax2(xma[1], x23a);
            opa[3] = __hmax2(x23a, u2h(dd.x));
            opb[0] = __hmax2(u2h(uu.y), x01b);
            opb[1] = __hmax2(x01b, xmb[2]);
            opb[2] = __hmax2(xmb[1], x23b);
            opb[3] = __hmax2(x23b, u2h(dd.y));
            #pragma unroll
            for (int i = 0; i < 4; i++) {
                __half2 d;
                d = __hsub2(ea[i], opa[i]);
                ska[i] = __hadd2(ska[i], __hfma2(ska[i], __hneg2(d), d));
                d = __hsub2(eb[i], opb[i]);
                skb[i] = __hadd2(skb[i], __hfma2(skb[i], __hneg2(d), d));
            }
        }
        #pragma unroll
        for (int i = 0; i < 4; i++) { ea[i] = ena[i]; eb[i] = enb[i]; }
    }

    // ---- partial sums over this thread's 4 center rows ----
    float sa = 0.f, sb = 0.f;
    if (centerW) {
        const float* oimg = isPred ? tgt  + (size_t)b * H * W
                                   : pred + (size_t)(b - 8) * H * W;
        const bool oSig = !isPred;
        const bool c0 = (unsigned)(gx0 + 0) < W;
        const bool c3 = (unsigned)(gx0 + 3) < W;
        #pragma unroll
        for (int i = 0; i < 4; i++) {
            const int gy = gy0 + i;
            if ((unsigned)gy < H) {
                float2 lo = __half22float2(ska[i]);
                float2 hi = __half22float2(skb[i]);
                const float* row = oimg + (size_t)gy * W;
                if (c0 & c3) {
                    float4 w = *reinterpret_cast<const float4*>(row + gx0);
                    if (oSig) { w.x = sig_(w.x); w.y = sig_(w.y); w.z = sig_(w.z); w.w = sig_(w.w); }
                    sa += lo.x * w.x + lo.y * w.y + hi.x * w.z + hi.y * w.w;
                    sb += lo.x + lo.y + hi.x + hi.y;
                } else {
                    float s[4] = { lo.x, lo.y, hi.x, hi.y };
                    #pragma unroll
                    for (int j = 0; j < 4; j++) {
                        if ((unsigned)(gx0 + j) < W) {
                            float w = row[gx0 + j];
                            if (oSig) w = sig_(w);
                            sa += s[j] * w;
                            sb += s[j];
                        }
                    }
                }
            }
        }
    }

    // ---- block reduction (shuffle-based, identical to round 15) ----
    #pragma unroll
    for (int o = 16; o; o >>= 1) {
        sa += __shfl_down_sync(0xffffffffu, sa, o);
        sb += __shfl_down_sync(0xffffffffu, sb, o);
    }
    float2* sred = (float2*)exA;
    if (lane == 0) sred[wid] = make_float2(sa, sb);
    __syncthreads();
    if (wid == 0) {
        float2 p = sred[lane];
        float a = p.x, c = p.y;
        #pragma unroll
        for (int o = 16; o; o >>= 1) {
            a += __shfl_down_sync(0xffffffffu, a, o);
            c += __shfl_down_sync(0xffffffffu, c, o);
        }
        if (lane == 0) {
            atomicAdd(&g_sums[isPred ? 0 : 2], a);
            atomicAdd(&g_sums[isPred ? 1 : 3], c);

            // ---- fused finalization: 1600th arrival computes the loss ----
            __threadfence();
            if (atomicAdd(&g_done, 1u) == NBLOCKS - 1) {
                float S1 = g_sums[0], S2 = g_sums[1], S3 = g_sums[2], S4 = g_sums[3];
                float tp = (S1 + 1.0f) / (S2 + 1.0f);
                float ts = (S3 + 1.0f) / (S4 + 1.0f);
                float cl = 2.0f * tp * ts / (tp + ts + 1e-7f);
                out[0] = 1.0f - cl;
                // self-clean for the next graph replay
                g_sums[0] = 0.f; g_sums[1] = 0.f; g_sums[2] = 0.f; g_sums[3] = 0.f;
                __threadfence();
                g_done = 0u;
            }
        }
    }
}

extern "C" void kernel_launch(void* const* d_in, const int* in_sizes, int n_in,
                              void* d_out, int out_size)
{
    const float* pred = (const float*)d_in[0];
    const float* tgt  = (const float*)d_in[1];
    float* out = (float*)d_out;

    size_t shmem = (size_t)4096 * sizeof(uint2);  // exA(16KB)+exB(16KB)
    cudaFuncSetAttribute(cl_main, cudaFuncAttributeMaxDynamicSharedMemorySize, (int)shmem);

    cl_main<<<dim3(G, G, NB), 1024, shmem>>>(pred, tgt, out);

    (void)in_sizes; (void)n_in; (void)out_size;
}

// round 17
// speedup vs baseline: 1.0623x; 1.0623x over previous
#include <cuda_runtime.h>
#include <cuda_fp16.h>
#include <cstdint>

#define H 1024
#define W 1024
#define TS 104          // square output tile (pixels)
#define G  10           // 10*104 = 1040 >= 1024 (both dims)
#define NB 16           // 8 pred + 8 target

typedef unsigned int u32;

__device__ float g_sums[4];

__device__ __forceinline__ float sig_(float x) { return 1.0f / (1.0f + __expf(-x)); }

__device__ __forceinline__ u32 h2u(__half2 h) { return *reinterpret_cast<u32*>(&h); }
__device__ __forceinline__ __half2 u2h(u32 u) { return *reinterpret_cast<__half2*>(&u); }

// load 4 fp32 px, pad image-OOB with +1.0 (acts as +inf for erode; data in (0,1))
__device__ __forceinline__ float4 load_row(const float* __restrict__ img, int gy, int gx0, bool doSig)
{
    float4 v;
    if ((unsigned)gy < H) {
        const float* row = img + (size_t)gy * W;
        if (gx0 >= 0 && gx0 + 3 < W) {
            v = *reinterpret_cast<const float4*>(row + gx0);
            if (doSig) { v.x = sig_(v.x); v.y = sig_(v.y); v.z = sig_(v.z); v.w = sig_(v.w); }
        } else {
            v.x = ((unsigned)(gx0+0) < W) ? (doSig ? sig_(row[gx0+0]) : row[gx0+0]) : 1.0f;
            v.y = ((unsigned)(gx0+1) < W) ? (doSig ? sig_(row[gx0+1]) : row[gx0+1]) : 1.0f;
            v.z = ((unsigned)(gx0+2) < W) ? (doSig ? sig_(row[gx0+2]) : row[gx0+2]) : 1.0f;
            v.w = ((unsigned)(gx0+3) < W) ? (doSig ? sig_(row[gx0+3]) : row[gx0+3]) : 1.0f;
        }
    } else {
        v = make_float4(1.f, 1.f, 1.f, 1.f);
    }
    return v;
}

// buffer: 128 rows x 128 cols (fp16); warp w owns rows 4w..4w+3; lane = 4-px group.
__global__ __launch_bounds__(1024, 1)
void cl_main(const float* __restrict__ pred, const float* __restrict__ tgt)
{
    extern __shared__ uint2 smem_[];
    uint2* exA = smem_;           // [64][32] erode rowmin boundary rows
    uint2* exB = smem_ + 2048;    // [64][32] dilate rowmax boundary rows

    const int tid  = threadIdx.x;
    const int lane = tid & 31;
    const int wid  = tid >> 5;
    const int bx = blockIdx.x, by = blockIdx.y, b = blockIdx.z;
    const bool isPred = (b < 8);
    const float* img = isPred ? pred + (size_t)b * H * W
                              : tgt  + (size_t)(b - 8) * H * W;

    const int gx0 = bx * TS - 12 + 4 * lane;
    const int gy0 = by * TS - 12 + 4 * wid;
    const bool thrOOB = ((unsigned)gy0 > (unsigned)(H - 4)) ||
                        ((unsigned)gx0 > (unsigned)(W - 4));

    // keep-masks per half2 (0xFFFF per in-image px)
    u32 kma[4], kmb[4];
    {
        const u32 ca = (((unsigned)(gx0+0) < W) ? 0x0000FFFFu : 0u)
                     | (((unsigned)(gx0+1) < W) ? 0xFFFF0000u : 0u);
        const u32 cb = (((unsigned)(gx0+2) < W) ? 0x0000FFFFu : 0u)
                     | (((unsigned)(gx0+3) < W) ? 0xFFFF0000u : 0u);
        #pragma unroll
        for (int i = 0; i < 4; i++) {
            const bool rv = (unsigned)(gy0 + i) < H;
            kma[i] = rv ? ca : 0u;
            kmb[i] = rv ? cb : 0u;
        }
    }
    const u32 PADHI = 0x3C003C00u;  // (+1,+1) fp16 (erode pad)
    const u32 PADLO = 0xBC00BC00u;  // (-1,-1) fp16 (dilate pad)

    // ---- load e_0 ----
    __half2 ea[4], eb[4];
    #pragma unroll
    for (int i = 0; i < 4; i++) {
        float4 v = load_row(img, gy0 + i, gx0, isPred);
        ea[i] = __floats2half2_rn(v.x, v.y);
        eb[i] = __floats2half2_rn(v.z, v.w);
    }

    __half2 ska[4], skb[4];
    const __half2 h2z = __float2half2_rn(0.f);
    #pragma unroll
    for (int i = 0; i < 4; i++) { ska[i] = h2z; skb[i] = h2z; }

    const int upIdx = ((wid == 0)  ? 1       : (wid - 1) * 2 + 1) * 32 + lane;
    const int dnIdx = ((wid == 31) ? wid * 2 : (wid + 1) * 2) * 32 + lane;
    const int sl0 = (wid * 2 + 0) * 32 + lane;
    const int sl1 = (wid * 2 + 1) * 32 + lane;
    const bool dilateW = (wid >= 2) && (wid <= 29);
    const bool centerW = (wid >= 3) && (wid <= 28) && (lane >= 3) && (lane <= 28);

    #pragma unroll
    for (int k = 0; k < 11; k++) {
        // ---- erode horizontal: shuffles + PRMT shifts + HMNMX2 ----
        __half2 rma[4], rmb[4];
        #pragma unroll
        for (int i = 0; i < 4; i++) {
            u32 ua = h2u(ea[i]), ub = h2u(eb[i]);
            u32 lw = __shfl_up_sync(0xffffffffu, ub, 1);
            u32 rx = __shfl_down_sync(0xffffffffu, ua, 1);
            u32 la = __byte_perm(lw, ua, 0x5432);   // (p-1,p0)
            u32 mi = __byte_perm(ua, ub, 0x5432);   // (p1,p2)
            u32 rb = __byte_perm(ub, rx, 0x5432);   // (p3,p4)
            rma[i] = __hmin2(__hmin2(u2h(la), ea[i]), u2h(mi));
            rmb[i] = __hmin2(__hmin2(u2h(mi), eb[i]), u2h(rb));
        }
        exA[sl0] = make_uint2(h2u(rma[0]), h2u(rmb[0]));
        exA[sl1] = make_uint2(h2u(rma[3]), h2u(rmb[3]));
        __syncthreads();
        const uint2 upu = exA[upIdx];
        const uint2 dnu = exA[dnIdx];

        // ---- erode vertical (registers, CSE) ----
        __half2 m01a = __hmin2(rma[0], rma[1]), m23a = __hmin2(rma[2], rma[3]);
        __half2 m01b = __hmin2(rmb[0], rmb[1]), m23b = __hmin2(rmb[2], rmb[3]);
        __half2 ena[4], enb[4];
        ena[0] = __hmin2(u2h(upu.x), m01a);
        ena[1] = __hmin2(m01a, rma[2]);
        ena[2] = __hmin2(rma[1], m23a);
        ena[3] = __hmin2(m23a, u2h(dnu.x));
        enb[0] = __hmin2(u2h(upu.y), m01b);
        enb[1] = __hmin2(m01b, rmb[2]);
        enb[2] = __hmin2(rmb[1], m23b);
        enb[3] = __hmin2(m23b, u2h(dnu.y));

        // ---- forcing (border threads): dilate view pad=-1, erode view pad=+1 ----
        __half2 eda[4], edb[4];
        if (thrOOB) {
            #pragma unroll
            for (int i = 0; i < 4; i++) {
                u32 xa = h2u(ena[i]), xb = h2u(enb[i]);
                eda[i] = u2h((xa & kma[i]) | (PADLO & ~kma[i]));
                edb[i] = u2h((xb & kmb[i]) | (PADLO & ~kmb[i]));
                ena[i] = u2h((xa & kma[i]) | (PADHI & ~kma[i]));
                enb[i] = u2h((xb & kmb[i]) | (PADHI & ~kmb[i]));
            }
        } else {
            #pragma unroll
            for (int i = 0; i < 4; i++) { eda[i] = ena[i]; edb[i] = enb[i]; }
        }

        // ---- dilate horizontal + exchange (warps near center) ----
        __half2 xma[4], xmb[4];
        if (dilateW) {
            #pragma unroll
            for (int i = 0; i < 4; i++) {
                u32 ua = h2u(eda[i]), ub = h2u(edb[i]);
                u32 lw = __shfl_up_sync(0xffffffffu, ub, 1);
                u32 rx = __shfl_down_sync(0xffffffffu, ua, 1);
                u32 la = __byte_perm(lw, ua, 0x5432);
                u32 mi = __byte_perm(ua, ub, 0x5432);
                u32 rb = __byte_perm(ub, rx, 0x5432);
                xma[i] = __hmax2(__hmax2(u2h(la), eda[i]), u2h(mi));
                xmb[i] = __hmax2(__hmax2(u2h(mi), edb[i]), u2h(rb));
            }
            exB[sl0] = make_uint2(h2u(xma[0]), h2u(xmb[0]));
            exB[sl1] = make_uint2(h2u(xma[3]), h2u(xmb[3]));
        }
        __syncthreads();

        // ---- dilate vertical -> open; delta; skel update (relu dropped: exact) ----
        if (centerW) {
            const uint2 uu = exB[upIdx];
            const uint2 dd = exB[dnIdx];
            __half2 x01a = __hmax2(xma[0], xma[1]), x23a = __hmax2(xma[2], xma[3]);
            __half2 x01b = __hmax2(xmb[0], xmb[1]), x23b = __hmax2(xmb[2], xmb[3]);
            __half2 opa[4], opb[4];
            opa[0] = __hmax2(u2h(uu.x), x01a);
            opa[1] = __hmax2(x01a, xma[2]);
            opa[2] = __hmax2(xma[1], x23a);
            opa[3] = __hmax2(x23a, u2h(dd.x));
            opb[0] = __hmax2(u2h(uu.y), x01b);
            opb[1] = __hmax2(x01b, xmb[2]);
            opb[2] = __hmax2(xmb[1], x23b);
            opb[3] = __hmax2(x23b, u2h(dd.y));
            #pragma unroll
            for (int i = 0; i < 4; i++) {
                __half2 d;
                d = __hsub2(ea[i], opa[i]);
                ska[i] = __hadd2(ska[i], __hfma2(ska[i], __hneg2(d), d));
                d = __hsub2(eb[i], opb[i]);
                skb[i] = __hadd2(skb[i], __hfma2(skb[i], __hneg2(d), d));
            }
        }
        #pragma unroll
        for (int i = 0; i < 4; i++) { ea[i] = ena[i]; eb[i] = enb[i]; }
    }

    // ---- partial sums over this thread's 4 center rows ----
    float sa = 0.f, sb = 0.f;
    if (centerW) {
        const float* oimg = isPred ? tgt  + (size_t)b * H * W
                                   : pred + (size_t)(b - 8) * H * W;
        const bool oSig = !isPred;
        const bool c0 = (unsigned)(gx0 + 0) < W;
        const bool c3 = (unsigned)(gx0 + 3) < W;
        #pragma unroll
        for (int i = 0; i < 4; i++) {
            const int gy = gy0 + i;
            if ((unsigned)gy < H) {
                float2 lo = __half22float2(ska[i]);
                float2 hi = __half22float2(skb[i]);
                const float* row = oimg + (size_t)gy * W;
                if (c0 & c3) {
                    float4 w = *reinterpret_cast<const float4*>(row + gx0);
                    if (oSig) { w.x = sig_(w.x); w.y = sig_(w.y); w.z = sig_(w.z); w.w = sig_(w.w); }
                    sa += lo.x * w.x + lo.y * w.y + hi.x * w.z + hi.y * w.w;
                    sb += lo.x + lo.y + hi.x + hi.y;
                } else {
                    float s[4] = { lo.x, lo.y, hi.x, hi.y };
                    #pragma unroll
                    for (int j = 0; j < 4; j++) {
                        if ((unsigned)(gx0 + j) < W) {
                            float w = row[gx0 + j];
                            if (oSig) w = sig_(w);
                            sa += s[j] * w;
                            sb += s[j];
                        }
                    }
                }
            }
        }
    }

    // ---- block reduction (reuse exA) ----
    #pragma unroll
    for (int o = 16; o; o >>= 1) {
        sa += __shfl_down_sync(0xffffffffu, sa, o);
        sb += __shfl_down_sync(0xffffffffu, sb, o);
    }
    float2* sred = (float2*)exA;
    if (lane == 0) sred[wid] = make_float2(sa, sb);
    __syncthreads();
    if (wid == 0) {
        float2 p = sred[lane];
        float a = p.x, c = p.y;
        #pragma unroll
        for (int o = 16; o; o >>= 1) {
            a += __shfl_down_sync(0xffffffffu, a, o);
            c += __shfl_down_sync(0xffffffffu, c, o);
        }
        if (lane == 0) {
            atomicAdd(&g_sums[isPred ? 0 : 2], a);
            atomicAdd(&g_sums[isPred ? 1 : 3], c);
        }
    }
}

__global__ void final_kernel(float* __restrict__ out) {
    float S1 = g_sums[0], S2 = g_sums[1], S3 = g_sums[2], S4 = g_sums[3];
    float tp = (S1 + 1.0f) / (S2 + 1.0f);
    float ts = (S3 + 1.0f) / (S4 + 1.0f);
    float cl = 2.0f * tp * ts / (tp + ts + 1e-7f);
    out[0] = 1.0f - cl;
    g_sums[0] = 0.f; g_sums[1] = 0.f; g_sums[2] = 0.f; g_sums[3] = 0.f;
}

extern "C" void kernel_launch(void* const* d_in, const int* in_sizes, int n_in,
                              void* d_out, int out_size)
{
    const float* pred = (const float*)d_in[0];
    const float* tgt  = (const float*)d_in[1];
    float* out = (float*)d_out;

    size_t shmem = (size_t)4096 * sizeof(uint2);  // exA(16KB)+exB(16KB)
    cudaFuncSetAttribute(cl_main, cudaFuncAttributeMaxDynamicSharedMemorySize, (int)shmem);

    cl_main<<<dim3(G, G, NB), 1024, shmem>>>(pred, tgt);
    final_kernel<<<1, 1>>>(out);

    (void)in_sizes; (void)n_in; (void)out_size;
}